// round 6
// baseline (speedup 1.0000x reference)
#include <cuda_runtime.h>
#include <cuda_bf16.h>
#include <math.h>
#include <stdint.h>

#define BATCH 1024
#define NC 32
#define LPRE 1041
#define LH 520
#define L1 257
#define L2 125
#define LP 31
#define LZ 12

// ---------------- scratch (device globals) ------------------------------------------
__device__ float g_filt[NC * 16];
__device__ float g_h[BATCH * NC * LH];            // pooled RAW conv (pre-BN), 68 MB
__device__ float g_p1[BATCH * NC * LP];
__device__ float g_p2[BATCH * NC * LP];
__device__ float g_psA[NC * BATCH];
__device__ float g_psqA[NC * BATCH];
__device__ float g_ps2[2 * NC * BATCH];
__device__ float g_psq2[2 * NC * BATCH];
__device__ float g_mean1[NC], g_rstd1[NC];
__device__ float g_mean2[NC], g_rstd2[NC];
__device__ float g_mean3[NC], g_rstd3[NC];
__device__ float g_z[BATCH * 768];
__device__ float g_z1[BATCH * 1024];
__device__ float g_z2[BATCH * 512];
__device__ float g_z3[BATCH * 128];

// ---------------- 1. Laplace filter bank --------------------------------------------
__global__ void k_filt(const float* __restrict__ la_a, const float* __restrict__ la_b) {
    int t = threadIdx.x;
    if (t >= NC * 16) return;
    int c = t >> 4, k = t & 15;
    const float wf = 314.1592653589793f;
    const float c1 = (float)(-0.03 / sqrt(1.0 - 0.03 * 0.03));
    float tt = (float)k / 15.0f;
    float p = tt - la_b[c] / la_a[c];
    float arg = wf * (p - 0.1f);
    g_filt[t] = 0.08f * expf(c1 * arg) * (-sinf(arg));
}

// ---------------- 2. fused conv + bias + stats + avgpool, all in registers ----------
// One block per batch row. Lane l owns conv outputs o0=16l+512j .. o0+16 (17, one
// overlap) -> 8 pool outputs in registers. x-window shared across 4 channels/warp.
__global__ void __launch_bounds__(256) k_convfuse(const float* __restrict__ x,
                                                  const float* __restrict__ la_bias) {
    __shared__ float sx[1072];               // x padded by 16 on each side
    __shared__ float sf[NC * 16];
    __shared__ float sb[NC];
    int b = blockIdx.x;
    int t = threadIdx.x;
    int l = t & 31, w = t >> 5;
    for (int i = t; i < NC * 16; i += 256) sf[i] = g_filt[i];
    if (t < NC) sb[t] = la_bias[t];
    for (int i = t; i < 1072; i += 256) {
        int xi = i - 16;
        sx[i] = (xi >= 0 && xi < 1024) ? x[b * 1024 + xi] : 0.0f;
    }
    __syncthreads();

    float s[4] = {0.f, 0.f, 0.f, 0.f}, sq[4] = {0.f, 0.f, 0.f, 0.f};
#pragma unroll
    for (int j = 0; j < 3; j++) {
        int o0 = 16 * l + 512 * j;
        if (o0 > 1040) continue;             // j=2: only lanes 0,1 active
        float xw[32];
#pragma unroll
        for (int q = 0; q < 8; q++) {
            float4 v = *(const float4*)&sx[o0 + 4 * q];
            xw[4 * q + 0] = v.x; xw[4 * q + 1] = v.y; xw[4 * q + 2] = v.z; xw[4 * q + 3] = v.w;
        }
        int p0 = 8 * l + 256 * j;
        bool wr = (p0 + 7 <= 519);
        bool full = (o0 + 15 <= 1040);
        for (int r = 0; r < 4; r++) {
            int c = w * 4 + r;
            float bias = sb[c];
            const float* fw = &sf[c * 16];
            float op[17];
#pragma unroll
            for (int q = 0; q < 17; q++) {
                float acc = bias;
#pragma unroll
                for (int k = 0; k < 16; k++) acc += xw[q + k] * fw[k];
                op[q] = acc;
            }
            if (full) {
#pragma unroll
                for (int q = 0; q < 16; q++) { s[r] += op[q]; sq[r] += op[q] * op[q]; }
            } else {
#pragma unroll
                for (int q = 0; q < 16; q++)
                    if (o0 + q <= 1040) { s[r] += op[q]; sq[r] += op[q] * op[q]; }
            }
            if (wr) {
                float4 pa, pb;
                pa.x = (op[0]  + op[1]  + op[2])  * (1.0f / 3.0f);
                pa.y = (op[2]  + op[3]  + op[4])  * (1.0f / 3.0f);
                pa.z = (op[4]  + op[5]  + op[6])  * (1.0f / 3.0f);
                pa.w = (op[6]  + op[7]  + op[8])  * (1.0f / 3.0f);
                pb.x = (op[8]  + op[9]  + op[10]) * (1.0f / 3.0f);
                pb.y = (op[10] + op[11] + op[12]) * (1.0f / 3.0f);
                pb.z = (op[12] + op[13] + op[14]) * (1.0f / 3.0f);
                pb.w = (op[14] + op[15] + op[16]) * (1.0f / 3.0f);
                float* dst = &g_h[(b * NC + c) * LH + p0];
                *(float4*)dst = pa;
                *(float4*)(dst + 4) = pb;
            }
        }
    }
#pragma unroll
    for (int r = 0; r < 4; r++) {
        float sv = s[r], sqv = sq[r];
#pragma unroll
        for (int off = 16; off > 0; off >>= 1) {
            sv  += __shfl_down_sync(0xffffffffu, sv, off);
            sqv += __shfl_down_sync(0xffffffffu, sqv, off);
        }
        if (l == 0) {
            int c = w * 4 + r;
            g_psA[c * BATCH + b] = sv;
            g_psqA[c * BATCH + b] = sqv;
        }
    }
}

// ---------------- 3. BN1 finalize ---------------------------------------------------
__global__ void __launch_bounds__(256) k_fin1() {
    int c = blockIdx.x, t = threadIdx.x;
    float s = 0.0f, sq = 0.0f;
    for (int i = t; i < BATCH; i += 256) { s += g_psA[c * BATCH + i]; sq += g_psqA[c * BATCH + i]; }
    __shared__ float ss[256], ssq[256];
    ss[t] = s; ssq[t] = sq;
    __syncthreads();
    for (int o = 128; o > 0; o >>= 1) {
        if (t < o) { ss[t] += ss[t + o]; ssq[t] += ssq[t + o]; }
        __syncthreads();
    }
    if (t == 0) {
        float n = (float)BATCH * (float)LPRE;
        float m = ss[0] / n;
        float v = ssq[0] / n - m * m;
        g_mean1[c] = m;
        g_rstd1[c] = rsqrtf(v + 1e-5f);
    }
}

// ---------------- 4. branches: warp-per-row, all-register conv1->conv2->pool --------
// Lane l computes conv1 i=8l..8l+13 (6 redundant vs neighbor), conv2 j=4l..4l+3,
// pool l. No smem, no block syncs. Lanes 0..30 active.
__global__ void __launch_bounds__(256) k_branches(
        const float* __restrict__ bn1_g, const float* __restrict__ bn1_b,
        const float* __restrict__ a1_w, const float* __restrict__ a1_b,
        const float* __restrict__ e1_w, const float* __restrict__ e1_b,
        const float* __restrict__ f1_w, const float* __restrict__ f1_b,
        const float* __restrict__ fa_w, const float* __restrict__ fa_b) {
    int t = threadIdx.x;
    int l = t & 31, w = t >> 5;
    int pr = blockIdx.x * 8 + w;             // 0 .. 32767
    int b = pr >> 5, c = pr & 31;

    float sc = g_rstd1[c] * bn1_g[c];
    float shv = bn1_b[c] - g_mean1[c] * sc;

    float hw[36];
    if (l < 31) {
        const float* row = &g_h[(b * NC + c) * LH + 16 * l];
#pragma unroll
        for (int q = 0; q < 9; q++) {
            float4 v = *(const float4*)&row[4 * q];
            hw[4 * q + 0] = v.x; hw[4 * q + 1] = v.y; hw[4 * q + 2] = v.z; hw[4 * q + 3] = v.w;
        }
    } else {
#pragma unroll
        for (int q = 0; q < 36; q++) hw[q] = 0.0f;
    }

#pragma unroll
    for (int br = 0; br < 2; br++) {
        float w1v[8], w2v[8], bias1, bias2;
        if (br == 0) {
            float sw = 0.0f;
#pragma unroll
            for (int k = 0; k < 8; k++) { float wv = a1_w[c * 8 + k]; w1v[k] = sc * wv; sw += wv; }
            bias1 = (a1_b[c] - sw) + shv * sw;                 // Always
#pragma unroll
            for (int k = 0; k < 8; k++) w2v[k] = e1_w[c * 8 + k];
            bias2 = 1.0f - e1_b[c];                            // Eventually
        } else {
            float sw = 0.0f;
#pragma unroll
            for (int k = 0; k < 8; k++) { float wv = f1_w[c * 8 + k]; w1v[k] = sc * wv; sw += wv; }
            bias1 = (1.0f - f1_b[c]) + shv * sw;               // Eventually
            float sw2 = 0.0f;
#pragma unroll
            for (int k = 0; k < 8; k++) { float wv = fa_w[c * 8 + k]; w2v[k] = wv; sw2 += wv; }
            bias2 = fa_b[c] - sw2;                             // Always
        }

        float a[14];
#pragma unroll
        for (int m = 0; m < 14; m++) {
            float acc = bias1;
#pragma unroll
            for (int k = 0; k < 8; k++) acc += hw[2 * m + k] * w1v[k];
            a[m] = fmaxf(acc, 0.0f);
        }
        float mx = 0.0f;
#pragma unroll
        for (int q = 0; q < 4; q++) {
            float e = bias2;
#pragma unroll
            for (int k = 0; k < 8; k++) e += a[2 * q + k] * w2v[k];
            e = fmaxf(e, 0.0f);
            mx = (q == 0) ? e : fmaxf(mx, e);
        }
        float s = 0.0f, sqv = 0.0f;
        if (l < 31) {
            float* pout = (br == 0) ? g_p1 : g_p2;
            pout[(b * NC + c) * LP + l] = mx;
            s = mx; sqv = mx * mx;
        }
#pragma unroll
        for (int off = 16; off > 0; off >>= 1) {
            s   += __shfl_down_sync(0xffffffffu, s, off);
            sqv += __shfl_down_sync(0xffffffffu, sqv, off);
        }
        if (l == 0) {
            g_ps2[(br * NC + c) * BATCH + b] = s;
            g_psq2[(br * NC + c) * BATCH + b] = sqv;
        }
    }
}

// ---------------- 5. BN2/BN3 finalize -----------------------------------------------
__global__ void __launch_bounds__(256) k_fin2() {
    int bc = blockIdx.x;
    int t = threadIdx.x;
    float s = 0.0f, sq = 0.0f;
    for (int i = t; i < BATCH; i += 256) { s += g_ps2[bc * BATCH + i]; sq += g_psq2[bc * BATCH + i]; }
    __shared__ float ss[256], ssq[256];
    ss[t] = s; ssq[t] = sq;
    __syncthreads();
    for (int o = 128; o > 0; o >>= 1) {
        if (t < o) { ss[t] += ss[t + o]; ssq[t] += ssq[t + o]; }
        __syncthreads();
    }
    if (t == 0) {
        float n = (float)BATCH * (float)LP;
        float m = ss[0] / n;
        float v = ssq[0] / n - m * m;
        int br = bc >> 5, c = bc & 31;
        if (br == 0) { g_mean2[c] = m; g_rstd2[c] = rsqrtf(v + 1e-5f); }
        else         { g_mean3[c] = m; g_rstd3[c] = rsqrtf(v + 1e-5f); }
    }
}

// ---------------- 6. BN + final eventually -> z (both branches, one launch) ---------
__global__ void __launch_bounds__(256) k_stage2(
        const float* __restrict__ g2, const float* __restrict__ be2,
        const float* __restrict__ w2, const float* __restrict__ bb2,
        const float* __restrict__ g3, const float* __restrict__ be3,
        const float* __restrict__ w3, const float* __restrict__ bb3) {
    int branch = blockIdx.y;
    int bc = blockIdx.x * blockDim.x + threadIdx.x;
    if (bc >= BATCH * NC) return;
    int b = bc >> 5, c = bc & (NC - 1);
    const float *p, *meanv, *rstdv, *g, *be, *w, *bb;
    int zbase;
    if (branch == 0) { p = g_p1; meanv = g_mean2; rstdv = g_rstd2; zbase = 0;
                       g = g2; be = be2; w = w2; bb = bb2; }
    else             { p = g_p2; meanv = g_mean3; rstdv = g_rstd3; zbase = 384;
                       g = g3; be = be3; w = w3; bb = bb3; }
    float sc = rstdv[c] * g[c];
    float sh = be[c] - meanv[c] * sc;
    float wv[8];
    float sw = 0.0f;
#pragma unroll
    for (int k = 0; k < 8; k++) { wv[k] = w[c * 8 + k] * sc; sw += w[c * 8 + k]; }
    float bias = (1.0f - bb[c]) + sh * sw;
    float y[LP];
    const float* row = &p[bc * LP];
#pragma unroll
    for (int i = 0; i < LP; i++) y[i] = row[i];
#pragma unroll
    for (int j = 0; j < LZ; j++) {
        float acc = bias;
#pragma unroll
        for (int k = 0; k < 8; k++) acc += y[2 * j + k] * wv[k];
        g_z[b * 768 + zbase + c * LZ + j] = fmaxf(acc, 0.0f);
    }
}

// ---------------- 7. TF32 split-precision tensor-core GEMM + bias + relu ------------
__device__ __forceinline__ void tf32split(float x, uint32_t& hi, uint32_t& lo) {
    uint32_t h;
    asm("cvt.rna.tf32.f32 %0, %1;" : "=r"(h) : "f"(x));
    hi = h;
    lo = __float_as_uint(x - __uint_as_float(h));
}
__device__ __forceinline__ void mma8(float* c, const uint32_t* a, const uint32_t* b) {
    asm volatile("mma.sync.aligned.m16n8k8.row.col.f32.tf32.tf32.f32 "
                 "{%0,%1,%2,%3},{%4,%5,%6,%7},{%8,%9},{%0,%1,%2,%3};"
                 : "+f"(c[0]), "+f"(c[1]), "+f"(c[2]), "+f"(c[3])
                 : "r"(a[0]), "r"(a[1]), "r"(a[2]), "r"(a[3]), "r"(b[0]), "r"(b[1]));
}

__global__ void __launch_bounds__(256) k_gemm_mma(int stage,
                                                  const float* __restrict__ W,
                                                  const float* __restrict__ bias,
                                                  int K, int N) {
    const float* A;
    float* C;
    if (stage == 0)      { A = g_z;  C = g_z1; }
    else if (stage == 1) { A = g_z1; C = g_z2; }
    else                 { A = g_z2; C = g_z3; }

    __shared__ float As[128 * 36];
    __shared__ float Bs[32 * 72];
    int tid = threadIdx.x;
    int lane = tid & 31, wid = tid >> 5;
    int wm = wid >> 1, wn = wid & 1;
    int m0 = blockIdx.y * 128, n0 = blockIdx.x * 64;

    float acc[2][4][4];
#pragma unroll
    for (int i = 0; i < 2; i++)
#pragma unroll
        for (int j = 0; j < 4; j++)
#pragma unroll
            for (int q = 0; q < 4; q++) acc[i][j][q] = 0.0f;

    for (int k0 = 0; k0 < K; k0 += 32) {
#pragma unroll
        for (int i = 0; i < 4; i++) {
            int idx = tid + 256 * i;
            int m = idx >> 3, k4 = (idx & 7) << 2;
            float4 v = *(const float4*)(A + (m0 + m) * K + k0 + k4);
            *(float4*)&As[m * 36 + k4] = v;
        }
#pragma unroll
        for (int i = 0; i < 2; i++) {
            int idx = tid + 256 * i;
            int k = idx >> 4, n4 = (idx & 15) << 2;
            *(float4*)&Bs[k * 72 + n4] = *(const float4*)(W + (k0 + k) * N + n0 + n4);
        }
        __syncthreads();
#pragma unroll
        for (int ks = 0; ks < 4; ks++) {
            int kk = ks * 8 + (lane & 3);
            int r0 = wm * 32 + (lane >> 2);
            uint32_t ahi[2][4], alo[2][4];
#pragma unroll
            for (int tm = 0; tm < 2; tm++) {
                int row = r0 + tm * 16;
                tf32split(As[row * 36 + kk],           ahi[tm][0], alo[tm][0]);
                tf32split(As[(row + 8) * 36 + kk],     ahi[tm][1], alo[tm][1]);
                tf32split(As[row * 36 + kk + 4],       ahi[tm][2], alo[tm][2]);
                tf32split(As[(row + 8) * 36 + kk + 4], ahi[tm][3], alo[tm][3]);
            }
            uint32_t bhi[4][2], blo[4][2];
            int cb = wn * 32 + (lane >> 2);
#pragma unroll
            for (int tn = 0; tn < 4; tn++) {
                tf32split(Bs[kk * 72 + cb + tn * 8],       bhi[tn][0], blo[tn][0]);
                tf32split(Bs[(kk + 4) * 72 + cb + tn * 8], bhi[tn][1], blo[tn][1]);
            }
#pragma unroll
            for (int tm = 0; tm < 2; tm++)
#pragma unroll
                for (int tn = 0; tn < 4; tn++) {
                    mma8(acc[tm][tn], ahi[tm], bhi[tn]);
                    mma8(acc[tm][tn], ahi[tm], blo[tn]);
                    mma8(acc[tm][tn], alo[tm], bhi[tn]);
                }
        }
        __syncthreads();
    }

#pragma unroll
    for (int tm = 0; tm < 2; tm++) {
        int row = m0 + wm * 32 + tm * 16 + (lane >> 2);
#pragma unroll
        for (int tn = 0; tn < 4; tn++) {
            int col = n0 + wn * 32 + tn * 8 + (lane & 3) * 2;
            float bv0 = bias[col], bv1 = bias[col + 1];
            C[row * N + col]           = fmaxf(acc[tm][tn][0] + bv0, 0.0f);
            C[row * N + col + 1]       = fmaxf(acc[tm][tn][1] + bv1, 0.0f);
            C[(row + 8) * N + col]     = fmaxf(acc[tm][tn][2] + bv0, 0.0f);
            C[(row + 8) * N + col + 1] = fmaxf(acc[tm][tn][3] + bv1, 0.0f);
        }
    }
}

// ---------------- 8. final tiny GEMM (K=128, N=10) ----------------------------------
__global__ void __launch_bounds__(256) k_gemm4(const float* __restrict__ W,
                                               const float* __restrict__ bias,
                                               float* __restrict__ out) {
    __shared__ float sw[128 * 10];
    __shared__ float sb[10];
    int t = threadIdx.x;
    for (int i = t; i < 1280; i += 256) sw[i] = W[i];
    if (t < 10) sb[t] = bias[t];
    __syncthreads();
    int idx = blockIdx.x * 256 + t;
    if (idx >= BATCH * 10) return;
    int m = idx / 10, n = idx % 10;
    const float* a = &g_z3[m * 128];
    float acc = sb[n];
#pragma unroll 16
    for (int k = 0; k < 128; k++) acc += a[k] * sw[k * 10 + n];
    out[idx] = fmaxf(acc, 0.0f);
}

// ---------------- host ---------------------------------------------------------------
extern "C" void kernel_launch(void* const* d_in, const int* in_sizes, int n_in,
                              void* d_out, int out_size) {
    const float* x       = (const float*)d_in[0];
    const float* la_a    = (const float*)d_in[1];
    const float* la_b    = (const float*)d_in[2];
    const float* la_bias = (const float*)d_in[3];
    const float* bn1_g   = (const float*)d_in[4];
    const float* bn1_b   = (const float*)d_in[5];
    const float* a1_w = (const float*)d_in[6];
    const float* a1_b = (const float*)d_in[7];
    const float* e1_w = (const float*)d_in[8];
    const float* e1_b = (const float*)d_in[9];
    const float* bn2_g = (const float*)d_in[10];
    const float* bn2_b = (const float*)d_in[11];
    const float* e2_w = (const float*)d_in[12];
    const float* e2_b = (const float*)d_in[13];
    const float* f1_w = (const float*)d_in[14];
    const float* f1_b = (const float*)d_in[15];
    const float* fa_w = (const float*)d_in[16];
    const float* fa_b = (const float*)d_in[17];
    const float* bn3_g = (const float*)d_in[18];
    const float* bn3_b = (const float*)d_in[19];
    const float* f2_w = (const float*)d_in[20];
    const float* f2_b = (const float*)d_in[21];
    const float* w1 = (const float*)d_in[22];
    const float* b1 = (const float*)d_in[23];
    const float* w2 = (const float*)d_in[24];
    const float* b2 = (const float*)d_in[25];
    const float* w3 = (const float*)d_in[26];
    const float* b3 = (const float*)d_in[27];
    const float* w4 = (const float*)d_in[28];
    const float* b4 = (const float*)d_in[29];
    float* out = (float*)d_out;

    k_filt<<<1, 512>>>(la_a, la_b);
    k_convfuse<<<BATCH, 256>>>(x, la_bias);
    k_fin1<<<NC, 256>>>();
    k_branches<<<BATCH * NC / 8, 256>>>(bn1_g, bn1_b, a1_w, a1_b, e1_w, e1_b,
                                        f1_w, f1_b, fa_w, fa_b);
    k_fin2<<<2 * NC, 256>>>();
    k_stage2<<<dim3(128, 2), 256>>>(bn2_g, bn2_b, e2_w, e2_b,
                                    bn3_g, bn3_b, f2_w, f2_b);

    k_gemm_mma<<<dim3(16, 8), 256>>>(0, w1, b1, 768, 1024);
    k_gemm_mma<<<dim3(8, 8),  256>>>(1, w2, b2, 1024, 512);
    k_gemm_mma<<<dim3(2, 8),  256>>>(2, w3, b3, 512, 128);
    k_gemm4<<<40, 256>>>(w4, b4, out);
}

// round 7
// speedup vs baseline: 1.2163x; 1.2163x over previous
#include <cuda_runtime.h>
#include <cuda_bf16.h>
#include <math.h>
#include <stdint.h>

#define BATCH 1024
#define NC 32
#define LPRE 1041
#define LH 520
#define L1 257
#define L2 125
#define LP 31
#define LZ 12

// ---------------- scratch (device globals) ------------------------------------------
__device__ float g_filt[NC * 16];
__device__ float g_h[BATCH * NC * LH];            // pooled RAW conv (pre-BN), 68 MB
__device__ float g_p1[BATCH * NC * LP];
__device__ float g_p2[BATCH * NC * LP];
__device__ float g_psA[NC * BATCH];
__device__ float g_psqA[NC * BATCH];
__device__ float g_ps2[2 * NC * BATCH];
__device__ float g_psq2[2 * NC * BATCH];
__device__ float g_mean1[NC], g_rstd1[NC];
__device__ float g_mean2[NC], g_rstd2[NC];
__device__ float g_mean3[NC], g_rstd3[NC];
__device__ float g_z[BATCH * 768];
__device__ float g_z1[BATCH * 1024];
__device__ float g_z2[BATCH * 512];
__device__ float g_z3[BATCH * 128];

// ---------------- 1. Laplace filter bank --------------------------------------------
__global__ void k_filt(const float* __restrict__ la_a, const float* __restrict__ la_b) {
    int t = threadIdx.x;
    if (t >= NC * 16) return;
    int c = t >> 4, k = t & 15;
    const float wf = 314.1592653589793f;
    const float c1 = (float)(-0.03 / sqrt(1.0 - 0.03 * 0.03));
    float tt = (float)k / 15.0f;
    float p = tt - la_b[c] / la_a[c];
    float arg = wf * (p - 0.1f);
    g_filt[t] = 0.08f * expf(c1 * arg) * (-sinf(arg));
}

// ---------------- 2. fused conv + bias + BN1 partial stats + avgpool (round-4 ver) --
#define SROW_STRIDE 1048
__global__ void __launch_bounds__(256) k_convfuse(const float* __restrict__ x,
                                                  const float* __restrict__ la_bias) {
    __shared__ float sx[1072];
    __shared__ float sf[NC * 16];
    __shared__ float sb[NC];
    __shared__ float srow[8 * SROW_STRIDE];
    int b = blockIdx.x;
    int t = threadIdx.x;
    int l = t & 31, w = t >> 5;
    for (int i = t; i < NC * 16; i += 256) sf[i] = g_filt[i];
    if (t < NC) sb[t] = la_bias[t];
    for (int i = t; i < 1072; i += 256) {
        int xi = i - 16;
        sx[i] = (xi >= 0 && xi < 1024) ? x[b * 1024 + xi] : 0.0f;
    }
    __syncthreads();

    float* my = &srow[w * SROW_STRIDE];
    for (int r = 0; r < 4; r++) {
        int c = w * 4 + r;
        float fw[16];
#pragma unroll
        for (int k = 0; k < 16; k++) fw[k] = sf[c * 16 + k];
        float bias = sb[c];
        float s = 0.0f, sq = 0.0f;
        for (int j = 0; j < 9; j++) {
            int o0 = 4 * l + 128 * j;
            if (o0 > 1040) break;
            float xw[20];
#pragma unroll
            for (int q = 0; q < 5; q++) {
                float4 v = *(const float4*)&sx[o0 + 4 * q];
                xw[4 * q + 0] = v.x; xw[4 * q + 1] = v.y; xw[4 * q + 2] = v.z; xw[4 * q + 3] = v.w;
            }
            float4 ov;
            float* op = (float*)&ov;
#pragma unroll
            for (int q = 0; q < 4; q++) {
                float acc = bias;
#pragma unroll
                for (int k = 0; k < 16; k++) acc += xw[q + k] * fw[k];
                op[q] = acc;
                if (o0 + q < LPRE) { s += acc; sq += acc * acc; }
            }
            *(float4*)&my[o0] = ov;
        }
        __syncwarp();
        for (int i = l; i < LH; i += 32) {
            float v = (my[2 * i] + my[2 * i + 1] + my[2 * i + 2]) * (1.0f / 3.0f);
            g_h[(b * NC + c) * LH + i] = v;
        }
#pragma unroll
        for (int off = 16; off > 0; off >>= 1) {
            s  += __shfl_down_sync(0xffffffffu, s, off);
            sq += __shfl_down_sync(0xffffffffu, sq, off);
        }
        if (l == 0) { g_psA[c * BATCH + b] = s; g_psqA[c * BATCH + b] = sq; }
        __syncwarp();
    }
}

// ---------------- 3. BN1 finalize ---------------------------------------------------
__global__ void __launch_bounds__(256) k_fin1() {
    int c = blockIdx.x, t = threadIdx.x;
    float s = 0.0f, sq = 0.0f;
    for (int i = t; i < BATCH; i += 256) { s += g_psA[c * BATCH + i]; sq += g_psqA[c * BATCH + i]; }
    __shared__ float ss[256], ssq[256];
    ss[t] = s; ssq[t] = sq;
    __syncthreads();
    for (int o = 128; o > 0; o >>= 1) {
        if (t < o) { ss[t] += ss[t + o]; ssq[t] += ssq[t + o]; }
        __syncthreads();
    }
    if (t == 0) {
        float n = (float)BATCH * (float)LPRE;
        float m = ss[0] / n;
        float v = ssq[0] / n - m * m;
        g_mean1[c] = m;
        g_rstd1[c] = rsqrtf(v + 1e-5f);
    }
}

// ---------------- 4. branches: warp-per-row, all-register conv1->conv2->pool --------
__global__ void __launch_bounds__(256) k_branches(
        const float* __restrict__ bn1_g, const float* __restrict__ bn1_b,
        const float* __restrict__ a1_w, const float* __restrict__ a1_b,
        const float* __restrict__ e1_w, const float* __restrict__ e1_b,
        const float* __restrict__ f1_w, const float* __restrict__ f1_b,
        const float* __restrict__ fa_w, const float* __restrict__ fa_b) {
    int t = threadIdx.x;
    int l = t & 31, w = t >> 5;
    int pr = blockIdx.x * 8 + w;
    int b = pr >> 5, c = pr & 31;

    float sc = g_rstd1[c] * bn1_g[c];
    float shv = bn1_b[c] - g_mean1[c] * sc;

    float hw[36];
    if (l < 31) {
        const float* row = &g_h[(b * NC + c) * LH + 16 * l];
#pragma unroll
        for (int q = 0; q < 9; q++) {
            float4 v = *(const float4*)&row[4 * q];
            hw[4 * q + 0] = v.x; hw[4 * q + 1] = v.y; hw[4 * q + 2] = v.z; hw[4 * q + 3] = v.w;
        }
    } else {
#pragma unroll
        for (int q = 0; q < 36; q++) hw[q] = 0.0f;
    }

#pragma unroll
    for (int br = 0; br < 2; br++) {
        float w1v[8], w2v[8], bias1, bias2;
        if (br == 0) {
            float sw = 0.0f;
#pragma unroll
            for (int k = 0; k < 8; k++) { float wv = a1_w[c * 8 + k]; w1v[k] = sc * wv; sw += wv; }
            bias1 = (a1_b[c] - sw) + shv * sw;
#pragma unroll
            for (int k = 0; k < 8; k++) w2v[k] = e1_w[c * 8 + k];
            bias2 = 1.0f - e1_b[c];
        } else {
            float sw = 0.0f;
#pragma unroll
            for (int k = 0; k < 8; k++) { float wv = f1_w[c * 8 + k]; w1v[k] = sc * wv; sw += wv; }
            bias1 = (1.0f - f1_b[c]) + shv * sw;
            float sw2 = 0.0f;
#pragma unroll
            for (int k = 0; k < 8; k++) { float wv = fa_w[c * 8 + k]; w2v[k] = wv; sw2 += wv; }
            bias2 = fa_b[c] - sw2;
        }

        float a[14];
#pragma unroll
        for (int m = 0; m < 14; m++) {
            float acc = bias1;
#pragma unroll
            for (int k = 0; k < 8; k++) acc += hw[2 * m + k] * w1v[k];
            a[m] = fmaxf(acc, 0.0f);
        }
        float mx = 0.0f;
#pragma unroll
        for (int q = 0; q < 4; q++) {
            float e = bias2;
#pragma unroll
            for (int k = 0; k < 8; k++) e += a[2 * q + k] * w2v[k];
            e = fmaxf(e, 0.0f);
            mx = (q == 0) ? e : fmaxf(mx, e);
        }
        float s = 0.0f, sqv = 0.0f;
        if (l < 31) {
            float* pout = (br == 0) ? g_p1 : g_p2;
            pout[(b * NC + c) * LP + l] = mx;
            s = mx; sqv = mx * mx;
        }
#pragma unroll
        for (int off = 16; off > 0; off >>= 1) {
            s   += __shfl_down_sync(0xffffffffu, s, off);
            sqv += __shfl_down_sync(0xffffffffu, sqv, off);
        }
        if (l == 0) {
            g_ps2[(br * NC + c) * BATCH + b] = s;
            g_psq2[(br * NC + c) * BATCH + b] = sqv;
        }
    }
}

// ---------------- 5. BN2/BN3 finalize -----------------------------------------------
__global__ void __launch_bounds__(256) k_fin2() {
    int bc = blockIdx.x;
    int t = threadIdx.x;
    float s = 0.0f, sq = 0.0f;
    for (int i = t; i < BATCH; i += 256) { s += g_ps2[bc * BATCH + i]; sq += g_psq2[bc * BATCH + i]; }
    __shared__ float ss[256], ssq[256];
    ss[t] = s; ssq[t] = sq;
    __syncthreads();
    for (int o = 128; o > 0; o >>= 1) {
        if (t < o) { ss[t] += ss[t + o]; ssq[t] += ssq[t + o]; }
        __syncthreads();
    }
    if (t == 0) {
        float n = (float)BATCH * (float)LP;
        float m = ss[0] / n;
        float v = ssq[0] / n - m * m;
        int br = bc >> 5, c = bc & 31;
        if (br == 0) { g_mean2[c] = m; g_rstd2[c] = rsqrtf(v + 1e-5f); }
        else         { g_mean3[c] = m; g_rstd3[c] = rsqrtf(v + 1e-5f); }
    }
}

// ---------------- 6. BN + final eventually -> z (both branches, one launch) ---------
__global__ void __launch_bounds__(256) k_stage2(
        const float* __restrict__ g2, const float* __restrict__ be2,
        const float* __restrict__ w2, const float* __restrict__ bb2,
        const float* __restrict__ g3, const float* __restrict__ be3,
        const float* __restrict__ w3, const float* __restrict__ bb3) {
    int branch = blockIdx.y;
    int bc = blockIdx.x * blockDim.x + threadIdx.x;
    if (bc >= BATCH * NC) return;
    int b = bc >> 5, c = bc & (NC - 1);
    const float *p, *meanv, *rstdv, *g, *be, *w, *bb;
    int zbase;
    if (branch == 0) { p = g_p1; meanv = g_mean2; rstdv = g_rstd2; zbase = 0;
                       g = g2; be = be2; w = w2; bb = bb2; }
    else             { p = g_p2; meanv = g_mean3; rstdv = g_rstd3; zbase = 384;
                       g = g3; be = be3; w = w3; bb = bb3; }
    float sc = rstdv[c] * g[c];
    float sh = be[c] - meanv[c] * sc;
    float wv[8];
    float sw = 0.0f;
#pragma unroll
    for (int k = 0; k < 8; k++) { wv[k] = w[c * 8 + k] * sc; sw += w[c * 8 + k]; }
    float bias = (1.0f - bb[c]) + sh * sw;
    float y[LP];
    const float* row = &p[bc * LP];
#pragma unroll
    for (int i = 0; i < LP; i++) y[i] = row[i];
#pragma unroll
    for (int j = 0; j < LZ; j++) {
        float acc = bias;
#pragma unroll
        for (int k = 0; k < 8; k++) acc += y[2 * j + k] * wv[k];
        g_z[b * 768 + zbase + c * LZ + j] = fmaxf(acc, 0.0f);
    }
}

// ---------------- 7. bf16 split-precision tensor-core GEMM + bias + relu ------------
// C = relu(A @ W + bias), A(1024,K), W(K,N). x = hi + lo (bf16 each);
// C ~= Ah*Bh + Ah*Bl + Al*Bh (residual ~2^-16). m16n8k16 mma, splits done once
// at smem-load time, packed bf16x2 along k, stride-20 words (conflict-free frags).
__device__ __forceinline__ uint32_t packbf(float x, float y) {
    __nv_bfloat162 p = __floats2bfloat162_rn(x, y);   // x -> low half (k even)
    return *(uint32_t*)&p;
}
__device__ __forceinline__ void mma16(float* c, const uint32_t* a, uint32_t b0, uint32_t b1) {
    asm volatile("mma.sync.aligned.m16n8k16.row.col.f32.bf16.bf16.f32 "
                 "{%0,%1,%2,%3},{%4,%5,%6,%7},{%8,%9},{%0,%1,%2,%3};"
                 : "+f"(c[0]), "+f"(c[1]), "+f"(c[2]), "+f"(c[3])
                 : "r"(a[0]), "r"(a[1]), "r"(a[2]), "r"(a[3]), "r"(b0), "r"(b1));
}

#define ASTR 20   // uint32 stride per row (16 k-pairs used + 4 pad)

__global__ void __launch_bounds__(256) k_gemm_bf16(int stage,
                                                   const float* __restrict__ W,
                                                   const float* __restrict__ bias,
                                                   int K, int N) {
    const float* A;
    float* C;
    if (stage == 0)      { A = g_z;  C = g_z1; }
    else if (stage == 1) { A = g_z1; C = g_z2; }
    else                 { A = g_z2; C = g_z3; }

    __shared__ uint32_t As_h[128 * ASTR];
    __shared__ uint32_t As_l[128 * ASTR];
    __shared__ uint32_t Bs_h[64 * ASTR];
    __shared__ uint32_t Bs_l[64 * ASTR];

    int tid = threadIdx.x;
    int lane = tid & 31, wid = tid >> 5;
    int g = lane >> 2, tg = lane & 3;
    int wm = wid >> 1, wn = wid & 1;          // 4x2 warps, warp tile 32x32
    int m0 = blockIdx.y * 128, n0 = blockIdx.x * 64;

    float acc[2][4][4];
#pragma unroll
    for (int i = 0; i < 2; i++)
#pragma unroll
        for (int j = 0; j < 4; j++)
#pragma unroll
            for (int q = 0; q < 4; q++) acc[i][j][q] = 0.0f;

    for (int k0 = 0; k0 < K; k0 += 32) {
        // --- load + split A tile (128 x 32) ---
#pragma unroll
        for (int i = 0; i < 4; i++) {
            int idx = tid + 256 * i;
            int m = idx >> 3, q = idx & 7;            // q: float4 index (k = 4q)
            float4 v = *(const float4*)(A + (m0 + m) * K + k0 + 4 * q);
            __nv_bfloat16 hx = __float2bfloat16_rn(v.x);
            __nv_bfloat16 hy = __float2bfloat16_rn(v.y);
            __nv_bfloat16 hz = __float2bfloat16_rn(v.z);
            __nv_bfloat16 hw2 = __float2bfloat16_rn(v.w);
            float lx = v.x - __bfloat162float(hx);
            float ly = v.y - __bfloat162float(hy);
            float lz = v.z - __bfloat162float(hz);
            float lw = v.w - __bfloat162float(hw2);
            __nv_bfloat162 ph0; ph0.x = hx; ph0.y = hy;
            __nv_bfloat162 ph1; ph1.x = hz; ph1.y = hw2;
            As_h[m * ASTR + 2 * q]     = *(uint32_t*)&ph0;
            As_h[m * ASTR + 2 * q + 1] = *(uint32_t*)&ph1;
            As_l[m * ASTR + 2 * q]     = packbf(lx, ly);
            As_l[m * ASTR + 2 * q + 1] = packbf(lz, lw);
        }
        // --- load + split + transpose B tile (32 x 64) -> Bs[n][kpair] ---
        {
            int p = tid >> 4;            // kpair 0..15
            int n4 = (tid & 15) * 4;     // 0..60
            float4 w0 = *(const float4*)(W + (k0 + 2 * p) * N + n0 + n4);
            float4 w1 = *(const float4*)(W + (k0 + 2 * p + 1) * N + n0 + n4);
            const float* e0 = (const float*)&w0;
            const float* e1 = (const float*)&w1;
#pragma unroll
            for (int j = 0; j < 4; j++) {
                float a0 = e0[j], a1 = e1[j];
                __nv_bfloat16 h0 = __float2bfloat16_rn(a0);
                __nv_bfloat16 h1 = __float2bfloat16_rn(a1);
                float l0 = a0 - __bfloat162float(h0);
                float l1 = a1 - __bfloat162float(h1);
                __nv_bfloat162 ph; ph.x = h0; ph.y = h1;
                Bs_h[(n4 + j) * ASTR + p] = *(uint32_t*)&ph;
                Bs_l[(n4 + j) * ASTR + p] = packbf(l0, l1);
            }
        }
        __syncthreads();

#pragma unroll
        for (int ks = 0; ks < 2; ks++) {
            int kb = ks * 8 + tg;
            uint32_t ah[2][4], al[2][4];
#pragma unroll
            for (int tm = 0; tm < 2; tm++) {
                int R = (wm * 32 + tm * 16 + g) * ASTR;
                ah[tm][0] = As_h[R + kb];
                ah[tm][1] = As_h[R + 8 * ASTR + kb];
                ah[tm][2] = As_h[R + kb + 4];
                ah[tm][3] = As_h[R + 8 * ASTR + kb + 4];
                al[tm][0] = As_l[R + kb];
                al[tm][1] = As_l[R + 8 * ASTR + kb];
                al[tm][2] = As_l[R + kb + 4];
                al[tm][3] = As_l[R + 8 * ASTR + kb + 4];
            }
#pragma unroll
            for (int tn = 0; tn < 4; tn++) {
                int Cb = (wn * 32 + tn * 8 + g) * ASTR;
                uint32_t bh0 = Bs_h[Cb + kb], bh1 = Bs_h[Cb + kb + 4];
                uint32_t bl0 = Bs_l[Cb + kb], bl1 = Bs_l[Cb + kb + 4];
#pragma unroll
                for (int tm = 0; tm < 2; tm++) {
                    mma16(acc[tm][tn], ah[tm], bh0, bh1);
                    mma16(acc[tm][tn], ah[tm], bl0, bl1);
                    mma16(acc[tm][tn], al[tm], bh0, bh1);
                }
            }
        }
        __syncthreads();
    }

    // epilogue: bias + relu
#pragma unroll
    for (int tm = 0; tm < 2; tm++) {
        int row = m0 + wm * 32 + tm * 16 + g;
#pragma unroll
        for (int tn = 0; tn < 4; tn++) {
            int col = n0 + wn * 32 + tn * 8 + tg * 2;
            float bv0 = bias[col], bv1 = bias[col + 1];
            C[row * N + col]           = fmaxf(acc[tm][tn][0] + bv0, 0.0f);
            C[row * N + col + 1]       = fmaxf(acc[tm][tn][1] + bv1, 0.0f);
            C[(row + 8) * N + col]     = fmaxf(acc[tm][tn][2] + bv0, 0.0f);
            C[(row + 8) * N + col + 1] = fmaxf(acc[tm][tn][3] + bv1, 0.0f);
        }
    }
}

// ---------------- 8. final tiny GEMM (K=128, N=10) ----------------------------------
__global__ void __launch_bounds__(256) k_gemm4(const float* __restrict__ W,
                                               const float* __restrict__ bias,
                                               float* __restrict__ out) {
    __shared__ float sw[128 * 10];
    __shared__ float sb[10];
    int t = threadIdx.x;
    for (int i = t; i < 1280; i += 256) sw[i] = W[i];
    if (t < 10) sb[t] = bias[t];
    __syncthreads();
    int idx = blockIdx.x * 256 + t;
    if (idx >= BATCH * 10) return;
    int m = idx / 10, n = idx % 10;
    const float* a = &g_z3[m * 128];
    float acc = sb[n];
#pragma unroll 16
    for (int k = 0; k < 128; k++) acc += a[k] * sw[k * 10 + n];
    out[idx] = fmaxf(acc, 0.0f);
}

// ---------------- host ---------------------------------------------------------------
extern "C" void kernel_launch(void* const* d_in, const int* in_sizes, int n_in,
                              void* d_out, int out_size) {
    const float* x       = (const float*)d_in[0];
    const float* la_a    = (const float*)d_in[1];
    const float* la_b    = (const float*)d_in[2];
    const float* la_bias = (const float*)d_in[3];
    const float* bn1_g   = (const float*)d_in[4];
    const float* bn1_b   = (const float*)d_in[5];
    const float* a1_w = (const float*)d_in[6];
    const float* a1_b = (const float*)d_in[7];
    const float* e1_w = (const float*)d_in[8];
    const float* e1_b = (const float*)d_in[9];
    const float* bn2_g = (const float*)d_in[10];
    const float* bn2_b = (const float*)d_in[11];
    const float* e2_w = (const float*)d_in[12];
    const float* e2_b = (const float*)d_in[13];
    const float* f1_w = (const float*)d_in[14];
    const float* f1_b = (const float*)d_in[15];
    const float* fa_w = (const float*)d_in[16];
    const float* fa_b = (const float*)d_in[17];
    const float* bn3_g = (const float*)d_in[18];
    const float* bn3_b = (const float*)d_in[19];
    const float* f2_w = (const float*)d_in[20];
    const float* f2_b = (const float*)d_in[21];
    const float* w1 = (const float*)d_in[22];
    const float* b1 = (const float*)d_in[23];
    const float* w2 = (const float*)d_in[24];
    const float* b2 = (const float*)d_in[25];
    const float* w3 = (const float*)d_in[26];
    const float* b3 = (const float*)d_in[27];
    const float* w4 = (const float*)d_in[28];
    const float* b4 = (const float*)d_in[29];
    float* out = (float*)d_out;

    k_filt<<<1, 512>>>(la_a, la_b);
    k_convfuse<<<BATCH, 256>>>(x, la_bias);
    k_fin1<<<NC, 256>>>();
    k_branches<<<BATCH * NC / 8, 256>>>(bn1_g, bn1_b, a1_w, a1_b, e1_w, e1_b,
                                        f1_w, f1_b, fa_w, fa_b);
    k_fin2<<<2 * NC, 256>>>();
    k_stage2<<<dim3(128, 2), 256>>>(bn2_g, bn2_b, e2_w, e2_b,
                                    bn3_g, bn3_b, f2_w, f2_b);

    k_gemm_bf16<<<dim3(16, 8), 256>>>(0, w1, b1, 768, 1024);
    k_gemm_bf16<<<dim3(8, 8),  256>>>(1, w2, b2, 1024, 512);
    k_gemm_bf16<<<dim3(2, 8),  256>>>(2, w3, b3, 512, 128);
    k_gemm4<<<40, 256>>>(w4, b4, out);
}

// round 8
// speedup vs baseline: 1.4968x; 1.2306x over previous
#include <cuda_runtime.h>
#include <cuda_bf16.h>
#include <math.h>
#include <stdint.h>

#define BATCH 1024
#define NC 32
#define LPRE 1041
#define LH 520
#define L1 257
#define L2 125
#define LP 31
#define LZ 12

// ---------------- scratch (device globals) ------------------------------------------
__device__ float g_h[BATCH * NC * LH];            // pooled RAW conv (pre-BN), 68 MB
__device__ float g_p1[BATCH * NC * LP];
__device__ float g_p2[BATCH * NC * LP];
__device__ float g_psA[NC * BATCH];
__device__ float g_psqA[NC * BATCH];
__device__ float g_ps2[2 * NC * BATCH];
__device__ float g_psq2[2 * NC * BATCH];
__device__ float g_mean1[NC], g_rstd1[NC];
__device__ float g_mean2[NC], g_rstd2[NC];
__device__ float g_mean3[NC], g_rstd3[NC];
// pre-split activations (packed bf16x2 hi/lo, [M][K/2] uint32)
__device__ uint32_t g_zh[BATCH * 384],  g_zl[BATCH * 384];
__device__ uint32_t g_z1h[BATCH * 512], g_z1l[BATCH * 512];
__device__ uint32_t g_z2h[BATCH * 256], g_z2l[BATCH * 256];
__device__ float g_z3[BATCH * 128];
// pre-split weights ([K/2][N] uint32)
__device__ uint32_t g_w1h[384 * 1024], g_w1l[384 * 1024];
__device__ uint32_t g_w2h[512 * 512],  g_w2l[512 * 512];
__device__ uint32_t g_w3h[256 * 128],  g_w3l[256 * 128];

// ---------------- helpers ------------------------------------------------------------
__device__ __forceinline__ uint32_t packbf(float x, float y) {
    __nv_bfloat162 p = __floats2bfloat162_rn(x, y);   // x -> low half (even k)
    return *(uint32_t*)&p;
}
__device__ __forceinline__ void splitpack(float x, float y, uint32_t& h, uint32_t& l) {
    __nv_bfloat16 hx = __float2bfloat16_rn(x);
    __nv_bfloat16 hy = __float2bfloat16_rn(y);
    __nv_bfloat162 ph; ph.x = hx; ph.y = hy;
    h = *(uint32_t*)&ph;
    l = packbf(x - __bfloat162float(hx), y - __bfloat162float(hy));
}
__device__ __forceinline__ void mma16(float* c, const uint32_t* a, uint32_t b0, uint32_t b1) {
    asm volatile("mma.sync.aligned.m16n8k16.row.col.f32.bf16.bf16.f32 "
                 "{%0,%1,%2,%3},{%4,%5,%6,%7},{%8,%9},{%0,%1,%2,%3};"
                 : "+f"(c[0]), "+f"(c[1]), "+f"(c[2]), "+f"(c[3])
                 : "r"(a[0]), "r"(a[1]), "r"(a[2]), "r"(a[3]), "r"(b0), "r"(b1));
}

// ---------------- 0. pre-split FC weights (once per launch, streaming) ---------------
__global__ void __launch_bounds__(256) k_split(const float* __restrict__ w1,
                                               const float* __restrict__ w2,
                                               const float* __restrict__ w3) {
    int idx = blockIdx.x * 256 + threadIdx.x;
    const int T1 = 384 * 1024, T2 = 512 * 512, T3 = 256 * 128;
    float a0, a1;
    uint32_t *H, *L;
    int o;
    if (idx < T1) {
        int p = idx >> 10, n = idx & 1023;
        a0 = w1[(2 * p) * 1024 + n]; a1 = w1[(2 * p + 1) * 1024 + n];
        H = g_w1h; L = g_w1l; o = idx;
    } else if (idx < T1 + T2) {
        int r = idx - T1;
        int p = r >> 9, n = r & 511;
        a0 = w2[(2 * p) * 512 + n]; a1 = w2[(2 * p + 1) * 512 + n];
        H = g_w2h; L = g_w2l; o = r;
    } else if (idx < T1 + T2 + T3) {
        int r = idx - T1 - T2;
        int p = r >> 7, n = r & 127;
        a0 = w3[(2 * p) * 128 + n]; a1 = w3[(2 * p + 1) * 128 + n];
        H = g_w3h; L = g_w3l; o = r;
    } else return;
    uint32_t hh, ll;
    splitpack(a0, a1, hh, ll);
    H[o] = hh; L[o] = ll;
}

// ---------------- 1+2. fused filter + conv + bias + BN1 stats + avgpool --------------
#define SROW_STRIDE 1048
__global__ void __launch_bounds__(256) k_convfuse(const float* __restrict__ x,
                                                  const float* __restrict__ la_bias,
                                                  const float* __restrict__ la_a,
                                                  const float* __restrict__ la_b) {
    __shared__ float sx[1072];
    __shared__ float sf[NC * 16];
    __shared__ float sb[NC];
    __shared__ float srow[8 * SROW_STRIDE];
    int b = blockIdx.x;
    int t = threadIdx.x;
    int l = t & 31, w = t >> 5;
    // laplace filter bank, computed in-block (cheap MUFU)
    for (int i = t; i < NC * 16; i += 256) {
        int c = i >> 4, k = i & 15;
        const float wf = 314.1592653589793f;
        const float c1 = (float)(-0.03 / sqrt(1.0 - 0.03 * 0.03));
        float tt = (float)k / 15.0f;
        float p = tt - la_b[c] / la_a[c];
        float arg = wf * (p - 0.1f);
        sf[i] = 0.08f * expf(c1 * arg) * (-sinf(arg));
    }
    if (t < NC) sb[t] = la_bias[t];
    for (int i = t; i < 1072; i += 256) {
        int xi = i - 16;
        sx[i] = (xi >= 0 && xi < 1024) ? x[b * 1024 + xi] : 0.0f;
    }
    __syncthreads();

    float* my = &srow[w * SROW_STRIDE];
    for (int r = 0; r < 4; r++) {
        int c = w * 4 + r;
        float fw[16];
#pragma unroll
        for (int k = 0; k < 16; k++) fw[k] = sf[c * 16 + k];
        float bias = sb[c];
        float s = 0.0f, sq = 0.0f;
        for (int j = 0; j < 9; j++) {
            int o0 = 4 * l + 128 * j;
            if (o0 > 1040) break;
            float xw[20];
#pragma unroll
            for (int q = 0; q < 5; q++) {
                float4 v = *(const float4*)&sx[o0 + 4 * q];
                xw[4 * q + 0] = v.x; xw[4 * q + 1] = v.y; xw[4 * q + 2] = v.z; xw[4 * q + 3] = v.w;
            }
            float4 ov;
            float* op = (float*)&ov;
#pragma unroll
            for (int q = 0; q < 4; q++) {
                float acc = bias;
#pragma unroll
                for (int k = 0; k < 16; k++) acc += xw[q + k] * fw[k];
                op[q] = acc;
                if (o0 + q < LPRE) { s += acc; sq += acc * acc; }
            }
            *(float4*)&my[o0] = ov;
        }
        __syncwarp();
        for (int i = l; i < LH; i += 32) {
            float v = (my[2 * i] + my[2 * i + 1] + my[2 * i + 2]) * (1.0f / 3.0f);
            g_h[(b * NC + c) * LH + i] = v;
        }
#pragma unroll
        for (int off = 16; off > 0; off >>= 1) {
            s  += __shfl_down_sync(0xffffffffu, s, off);
            sq += __shfl_down_sync(0xffffffffu, sq, off);
        }
        if (l == 0) { g_psA[c * BATCH + b] = s; g_psqA[c * BATCH + b] = sq; }
        __syncwarp();
    }
}

// ---------------- 3. BN1 finalize ---------------------------------------------------
__global__ void __launch_bounds__(256) k_fin1() {
    int c = blockIdx.x, t = threadIdx.x;
    float s = 0.0f, sq = 0.0f;
    for (int i = t; i < BATCH; i += 256) { s += g_psA[c * BATCH + i]; sq += g_psqA[c * BATCH + i]; }
    __shared__ float ss[256], ssq[256];
    ss[t] = s; ssq[t] = sq;
    __syncthreads();
    for (int o = 128; o > 0; o >>= 1) {
        if (t < o) { ss[t] += ss[t + o]; ssq[t] += ssq[t + o]; }
        __syncthreads();
    }
    if (t == 0) {
        float n = (float)BATCH * (float)LPRE;
        float m = ss[0] / n;
        float v = ssq[0] / n - m * m;
        g_mean1[c] = m;
        g_rstd1[c] = rsqrtf(v + 1e-5f);
    }
}

// ---------------- 4. branches: shuffle-borrowed windows, all-register chain ----------
__global__ void __launch_bounds__(256) k_branches(
        const float* __restrict__ bn1_g, const float* __restrict__ bn1_b,
        const float* __restrict__ a1_w, const float* __restrict__ a1_b,
        const float* __restrict__ e1_w, const float* __restrict__ e1_b,
        const float* __restrict__ f1_w, const float* __restrict__ f1_b,
        const float* __restrict__ fa_w, const float* __restrict__ fa_b) {
    int t = threadIdx.x;
    int l = t & 31, w = t >> 5;
    int pr = blockIdx.x * 8 + w;
    int b = pr >> 5, c = pr & 31;

    float sc = g_rstd1[c] * bn1_g[c];
    float shv = bn1_b[c] - g_mean1[c] * sc;

    // lane l loads h[16l .. 16l+19] (all lanes in-bounds: 16*31+19 = 515 < 520)
    float hw[34];
    {
        const float* row = &g_h[(b * NC + c) * LH + 16 * l];
#pragma unroll
        for (int q = 0; q < 5; q++) {
            float4 v = *(const float4*)&row[4 * q];
            hw[4 * q + 0] = v.x; hw[4 * q + 1] = v.y; hw[4 * q + 2] = v.z; hw[4 * q + 3] = v.w;
        }
    }
    // borrow h[16l+20 .. 16l+33] = lane(l+1)'s elements 4..17
#pragma unroll
    for (int q = 0; q < 14; q++)
        hw[20 + q] = __shfl_down_sync(0xffffffffu, hw[4 + q], 1);

#pragma unroll
    for (int br = 0; br < 2; br++) {
        float w1v[8], w2v[8], bias1, bias2;
        if (br == 0) {
            float sw = 0.0f;
#pragma unroll
            for (int k = 0; k < 8; k++) { float wv = a1_w[c * 8 + k]; w1v[k] = sc * wv; sw += wv; }
            bias1 = (a1_b[c] - sw) + shv * sw;                 // Always
#pragma unroll
            for (int k = 0; k < 8; k++) w2v[k] = e1_w[c * 8 + k];
            bias2 = 1.0f - e1_b[c];                            // Eventually
        } else {
            float sw = 0.0f;
#pragma unroll
            for (int k = 0; k < 8; k++) { float wv = f1_w[c * 8 + k]; w1v[k] = sc * wv; sw += wv; }
            bias1 = (1.0f - f1_b[c]) + shv * sw;               // Eventually
            float sw2 = 0.0f;
#pragma unroll
            for (int k = 0; k < 8; k++) { float wv = fa_w[c * 8 + k]; w2v[k] = wv; sw2 += wv; }
            bias2 = fa_b[c] - sw2;                             // Always
        }

        float a[14];
#pragma unroll
        for (int m = 0; m < 14; m++) {
            float acc = bias1;
#pragma unroll
            for (int k = 0; k < 8; k++) acc += hw[2 * m + k] * w1v[k];
            a[m] = fmaxf(acc, 0.0f);
        }
        float mx = 0.0f;
#pragma unroll
        for (int q = 0; q < 4; q++) {
            float e = bias2;
#pragma unroll
            for (int k = 0; k < 8; k++) e += a[2 * q + k] * w2v[k];
            e = fmaxf(e, 0.0f);
            mx = (q == 0) ? e : fmaxf(mx, e);
        }
        float s = 0.0f, sqv = 0.0f;
        if (l < 31) {
            float* pout = (br == 0) ? g_p1 : g_p2;
            pout[(b * NC + c) * LP + l] = mx;
            s = mx; sqv = mx * mx;
        }
#pragma unroll
        for (int off = 16; off > 0; off >>= 1) {
            s   += __shfl_down_sync(0xffffffffu, s, off);
            sqv += __shfl_down_sync(0xffffffffu, sqv, off);
        }
        if (l == 0) {
            g_ps2[(br * NC + c) * BATCH + b] = s;
            g_psq2[(br * NC + c) * BATCH + b] = sqv;
        }
    }
}

// ---------------- 5. BN2/BN3 finalize -----------------------------------------------
__global__ void __launch_bounds__(256) k_fin2() {
    int bc = blockIdx.x;
    int t = threadIdx.x;
    float s = 0.0f, sq = 0.0f;
    for (int i = t; i < BATCH; i += 256) { s += g_ps2[bc * BATCH + i]; sq += g_psq2[bc * BATCH + i]; }
    __shared__ float ss[256], ssq[256];
    ss[t] = s; ssq[t] = sq;
    __syncthreads();
    for (int o = 128; o > 0; o >>= 1) {
        if (t < o) { ss[t] += ss[t + o]; ssq[t] += ssq[t + o]; }
        __syncthreads();
    }
    if (t == 0) {
        float n = (float)BATCH * (float)LP;
        float m = ss[0] / n;
        float v = ssq[0] / n - m * m;
        int br = bc >> 5, c = bc & 31;
        if (br == 0) { g_mean2[c] = m; g_rstd2[c] = rsqrtf(v + 1e-5f); }
        else         { g_mean3[c] = m; g_rstd3[c] = rsqrtf(v + 1e-5f); }
    }
}

// ---------------- 6. BN + final eventually -> pre-split z ---------------------------
__global__ void __launch_bounds__(256) k_stage2(
        const float* __restrict__ g2, const float* __restrict__ be2,
        const float* __restrict__ w2, const float* __restrict__ bb2,
        const float* __restrict__ g3, const float* __restrict__ be3,
        const float* __restrict__ w3, const float* __restrict__ bb3) {
    int branch = blockIdx.y;
    int bc = blockIdx.x * blockDim.x + threadIdx.x;
    if (bc >= BATCH * NC) return;
    int b = bc >> 5, c = bc & (NC - 1);
    const float *p, *meanv, *rstdv, *g, *be, *w, *bb;
    int zhalf;
    if (branch == 0) { p = g_p1; meanv = g_mean2; rstdv = g_rstd2; zhalf = 0;
                       g = g2; be = be2; w = w2; bb = bb2; }
    else             { p = g_p2; meanv = g_mean3; rstdv = g_rstd3; zhalf = 192;
                       g = g3; be = be3; w = w3; bb = bb3; }
    float sc = rstdv[c] * g[c];
    float sh = be[c] - meanv[c] * sc;
    float wv[8];
    float sw = 0.0f;
#pragma unroll
    for (int k = 0; k < 8; k++) { wv[k] = w[c * 8 + k] * sc; sw += w[c * 8 + k]; }
    float bias = (1.0f - bb[c]) + sh * sw;
    float y[LP];
    const float* row = &p[bc * LP];
#pragma unroll
    for (int i = 0; i < LP; i++) y[i] = row[i];
    int obase = b * 384 + zhalf + c * (LZ / 2);
#pragma unroll
    for (int j2 = 0; j2 < LZ / 2; j2++) {
        float a0 = bias, a1 = bias;
#pragma unroll
        for (int k = 0; k < 8; k++) {
            a0 += y[4 * j2 + k] * wv[k];
            a1 += y[4 * j2 + 2 + k] * wv[k];
        }
        a0 = fmaxf(a0, 0.0f);
        a1 = fmaxf(a1, 0.0f);
        uint32_t hh, ll;
        splitpack(a0, a1, hh, ll);
        g_zh[obase + j2] = hh;
        g_zl[obase + j2] = ll;
    }
}

// ---------------- 7. pre-split bf16 tensor-core GEMM, double-buffered ---------------
// C = relu(A @ W + bias); A,W pre-split into bf16 hi/lo. 3 passes (AhBh+AhBl+AlBh).
// A smem [m][kp] stride 20 (conflict-free frags); B smem [kp][n] stride 72.
template<int STAGE>
__global__ void __launch_bounds__(256) k_gemm_bf16(const float* __restrict__ bias) {
    constexpr int KP = STAGE == 0 ? 384 : (STAGE == 1 ? 512 : 256);
    constexpr int N  = STAGE == 0 ? 1024 : (STAGE == 1 ? 512 : 128);
    constexpr int BN = STAGE == 0 ? 64 : (STAGE == 1 ? 32 : 16);
    constexpr int TN = BN / 16;
    constexpr int ITERS = KP / 16;
    constexpr int BTH = 4 * BN;

    const uint32_t* Ah = STAGE == 0 ? g_zh  : (STAGE == 1 ? g_z1h : g_z2h);
    const uint32_t* Al = STAGE == 0 ? g_zl  : (STAGE == 1 ? g_z1l : g_z2l);
    const uint32_t* Bh = STAGE == 0 ? g_w1h : (STAGE == 1 ? g_w2h : g_w3h);
    const uint32_t* Bl = STAGE == 0 ? g_w1l : (STAGE == 1 ? g_w2l : g_w3l);

    __shared__ uint32_t As_h[128 * 20], As_l[128 * 20];
    __shared__ uint32_t Bs_h[16 * 72],  Bs_l[16 * 72];

    int tid = threadIdx.x, lane = tid & 31, wid = tid >> 5;
    int gq = lane >> 2, tg = lane & 3;
    int wm = wid >> 1, wn = wid & 1;
    int m0 = blockIdx.y * 128, n0 = blockIdx.x * BN;

    int am[2], aq[2];
#pragma unroll
    for (int i = 0; i < 2; i++) { int lin = tid + 256 * i; am[i] = lin >> 2; aq[i] = (lin & 3) * 4; }
    bool bact = tid < BTH;
    int bp = tid / (BN / 4);
    int bn4 = (tid % (BN / 4)) * 4;

    float acc[2][TN][4] = {};

    uint4 pah[2], pal[2], pbh = {}, pbl = {};
#pragma unroll
    for (int i = 0; i < 2; i++) {
        pah[i] = *(const uint4*)&Ah[(m0 + am[i]) * KP + aq[i]];
        pal[i] = *(const uint4*)&Al[(m0 + am[i]) * KP + aq[i]];
    }
    if (bact) {
        pbh = *(const uint4*)&Bh[bp * N + n0 + bn4];
        pbl = *(const uint4*)&Bl[bp * N + n0 + bn4];
    }

    for (int it = 0; it < ITERS; it++) {
#pragma unroll
        for (int i = 0; i < 2; i++) {
            *(uint4*)&As_h[am[i] * 20 + aq[i]] = pah[i];
            *(uint4*)&As_l[am[i] * 20 + aq[i]] = pal[i];
        }
        if (bact) {
            *(uint4*)&Bs_h[bp * 72 + bn4] = pbh;
            *(uint4*)&Bs_l[bp * 72 + bn4] = pbl;
        }
        __syncthreads();
        if (it + 1 < ITERS) {
            int kp0 = (it + 1) * 16;
#pragma unroll
            for (int i = 0; i < 2; i++) {
                pah[i] = *(const uint4*)&Ah[(m0 + am[i]) * KP + kp0 + aq[i]];
                pal[i] = *(const uint4*)&Al[(m0 + am[i]) * KP + kp0 + aq[i]];
            }
            if (bact) {
                pbh = *(const uint4*)&Bh[(kp0 + bp) * N + n0 + bn4];
                pbl = *(const uint4*)&Bl[(kp0 + bp) * N + n0 + bn4];
            }
        }
#pragma unroll
        for (int ks = 0; ks < 2; ks++) {
            int kb = ks * 8 + tg;
            uint32_t ah[2][4], al[2][4];
#pragma unroll
            for (int tm = 0; tm < 2; tm++) {
                int R = (wm * 32 + tm * 16 + gq) * 20;
                ah[tm][0] = As_h[R + kb];       ah[tm][1] = As_h[R + 160 + kb];
                ah[tm][2] = As_h[R + kb + 4];   ah[tm][3] = As_h[R + 160 + kb + 4];
                al[tm][0] = As_l[R + kb];       al[tm][1] = As_l[R + 160 + kb];
                al[tm][2] = As_l[R + kb + 4];   al[tm][3] = As_l[R + 160 + kb + 4];
            }
#pragma unroll
            for (int tn = 0; tn < TN; tn++) {
                int nIdx = wn * (BN / 2) + tn * 8 + gq;
                uint32_t bh0 = Bs_h[kb * 72 + nIdx], bh1 = Bs_h[(kb + 4) * 72 + nIdx];
                uint32_t bl0 = Bs_l[kb * 72 + nIdx], bl1 = Bs_l[(kb + 4) * 72 + nIdx];
#pragma unroll
                for (int tm = 0; tm < 2; tm++) {
                    mma16(acc[tm][tn], ah[tm], bh0, bh1);
                    mma16(acc[tm][tn], ah[tm], bl0, bl1);
                    mma16(acc[tm][tn], al[tm], bh0, bh1);
                }
            }
        }
        __syncthreads();
    }

    // epilogue: bias + relu; stages 0/1 write pre-split next-A, stage 2 writes fp32
#pragma unroll
    for (int tm = 0; tm < 2; tm++) {
        int row = m0 + wm * 32 + tm * 16 + gq;
#pragma unroll
        for (int tn = 0; tn < TN; tn++) {
            int col = n0 + wn * (BN / 2) + tn * 8 + tg * 2;
            float bv0 = bias[col], bv1 = bias[col + 1];
            float v0 = fmaxf(acc[tm][tn][0] + bv0, 0.0f);
            float v1 = fmaxf(acc[tm][tn][1] + bv1, 0.0f);
            float v2 = fmaxf(acc[tm][tn][2] + bv0, 0.0f);
            float v3 = fmaxf(acc[tm][tn][3] + bv1, 0.0f);
            if (STAGE < 2) {
                constexpr int KPo = N / 2;
                uint32_t* Ch = STAGE == 0 ? g_z1h : g_z2h;
                uint32_t* Cl = STAGE == 0 ? g_z1l : g_z2l;
                uint32_t hh, ll;
                splitpack(v0, v1, hh, ll);
                Ch[row * KPo + col / 2] = hh;
                Cl[row * KPo + col / 2] = ll;
                splitpack(v2, v3, hh, ll);
                Ch[(row + 8) * KPo + col / 2] = hh;
                Cl[(row + 8) * KPo + col / 2] = ll;
            } else {
                g_z3[row * N + col] = v0;
                g_z3[row * N + col + 1] = v1;
                g_z3[(row + 8) * N + col] = v2;
                g_z3[(row + 8) * N + col + 1] = v3;
            }
        }
    }
}

// ---------------- 8. final tiny GEMM (K=128, N=10) ----------------------------------
__global__ void __launch_bounds__(256) k_gemm4(const float* __restrict__ W,
                                               const float* __restrict__ bias,
                                               float* __restrict__ out) {
    __shared__ float sw[128 * 10];
    __shared__ float sb[10];
    int t = threadIdx.x;
    for (int i = t; i < 1280; i += 256) sw[i] = W[i];
    if (t < 10) sb[t] = bias[t];
    __syncthreads();
    int idx = blockIdx.x * 256 + t;
    if (idx >= BATCH * 10) return;
    int m = idx / 10, n = idx % 10;
    const float* a = &g_z3[m * 128];
    float acc = sb[n];
#pragma unroll 16
    for (int k = 0; k < 128; k++) acc += a[k] * sw[k * 10 + n];
    out[idx] = fmaxf(acc, 0.0f);
}

// ---------------- host ---------------------------------------------------------------
extern "C" void kernel_launch(void* const* d_in, const int* in_sizes, int n_in,
                              void* d_out, int out_size) {
    const float* x       = (const float*)d_in[0];
    const float* la_a    = (const float*)d_in[1];
    const float* la_b    = (const float*)d_in[2];
    const float* la_bias = (const float*)d_in[3];
    const float* bn1_g   = (const float*)d_in[4];
    const float* bn1_b   = (const float*)d_in[5];
    const float* a1_w = (const float*)d_in[6];
    const float* a1_b = (const float*)d_in[7];
    const float* e1_w = (const float*)d_in[8];
    const float* e1_b = (const float*)d_in[9];
    const float* bn2_g = (const float*)d_in[10];
    const float* bn2_b = (const float*)d_in[11];
    const float* e2_w = (const float*)d_in[12];
    const float* e2_b = (const float*)d_in[13];
    const float* f1_w = (const float*)d_in[14];
    const float* f1_b = (const float*)d_in[15];
    const float* fa_w = (const float*)d_in[16];
    const float* fa_b = (const float*)d_in[17];
    const float* bn3_g = (const float*)d_in[18];
    const float* bn3_b = (const float*)d_in[19];
    const float* f2_w = (const float*)d_in[20];
    const float* f2_b = (const float*)d_in[21];
    const float* w1 = (const float*)d_in[22];
    const float* b1 = (const float*)d_in[23];
    const float* w2 = (const float*)d_in[24];
    const float* b2 = (const float*)d_in[25];
    const float* w3 = (const float*)d_in[26];
    const float* b3 = (const float*)d_in[27];
    const float* w4 = (const float*)d_in[28];
    const float* b4 = (const float*)d_in[29];
    float* out = (float*)d_out;

    k_split<<<2688, 256>>>(w1, w2, w3);
    k_convfuse<<<BATCH, 256>>>(x, la_bias, la_a, la_b);
    k_fin1<<<NC, 256>>>();
    k_branches<<<BATCH * NC / 8, 256>>>(bn1_g, bn1_b, a1_w, a1_b, e1_w, e1_b,
                                        f1_w, f1_b, fa_w, fa_b);
    k_fin2<<<2 * NC, 256>>>();
    k_stage2<<<dim3(128, 2), 256>>>(bn2_g, bn2_b, e2_w, e2_b,
                                    bn3_g, bn3_b, f2_w, f2_b);

    k_gemm_bf16<0><<<dim3(16, 8), 256>>>(b1);
    k_gemm_bf16<1><<<dim3(16, 8), 256>>>(b2);
    k_gemm_bf16<2><<<dim3(8, 8),  256>>>(b3);
    k_gemm4<<<40, 256>>>(w4, b4, out);
}